// round 3
// baseline (speedup 1.0000x reference)
#include <cuda_runtime.h>
#include <cmath>
#include <stdint.h>

#define NLEV   16
#define NDENSE 5
#define TSIZE  (1u << 19)
#define HID    64
#define ENC    32
#define P2     2654435761u
#define P3     805459861u

typedef unsigned long long u64;

// Padded x-pair tables for the dense levels: Q[i] = (tab[i], tab[i+1]).
#define QCAP 339072
__device__ float4 g_Q[QCAP];

// Weights in constant memory: warp-uniform reads go through the uniform-const
// port (LDCU), completely off the saturated l1tex pipe.
__constant__ float cW0[ENC * HID];   //  8 KB
__constant__ float cW1[HID * HID];   // 16 KB
__constant__ float cW2[HID];         // 256 B

struct LevelParams {
    float    resf[NLEV];
    unsigned s1[NLEV];
    unsigned s2[NLEV];
    unsigned qoff[NDENSE];
    unsigned qcnt[NDENSE];
};

__device__ __forceinline__ u64 pk2(float a, float b) {
    u64 r; asm("mov.b64 %0, {%1,%2};" : "=l"(r) : "f"(a), "f"(b)); return r;
}
__device__ __forceinline__ void upk2(u64 v, float& a, float& b) {
    asm("mov.b64 {%0,%1}, %2;" : "=f"(a), "=f"(b) : "l"(v));
}
// Blackwell packed fp32 FMA (FFMA2), only reachable via PTX.
__device__ __forceinline__ u64 ffma2(u64 a, u64 b, u64 c) {
    u64 d; asm("fma.rn.f32x2 %0, %1, %2, %3;" : "=l"(d) : "l"(a), "l"(b), "l"(c)); return d;
}

// ---------- prologue: build dense pair tables ----------
__global__ void build_q(const float2* __restrict__ tables, LevelParams lp, unsigned total) {
    unsigned i = blockIdx.x * blockDim.x + threadIdx.x;
    if (i >= total) return;
    int l = 0; unsigned base = 0;
#pragma unroll
    for (int k = 0; k < NDENSE; k++) {
        unsigned o = lp.qoff[k];
        if (i >= o && i < o + lp.qcnt[k]) { l = k; base = o; }
    }
    unsigned j = i - base;
    const float2* __restrict__ tab = tables + (size_t)l * TSIZE;
    float2 a = __ldg(&tab[j]);
    float2 b = __ldg(&tab[j + 1]);
    g_Q[i] = make_float4(a.x, a.y, b.x, b.y);
}

// ---------- one level: trilinear + stream through layer 0 (weights from cbank) ----------
__device__ __forceinline__ void level_accumulate(
    int l, const float2 f0[4], const float2 f1[4],
    float fx, float fy, float fz, u64 acc[HID / 2])
{
    const float gy = 1.0f - fy, gz = 1.0f - fz, gx = 1.0f - fx;
    float wyz[4];
    wyz[0] = gy * gz;  wyz[1] = gy * fz;  wyz[2] = fy * gz;  wyz[3] = fy * fz;

    float e0 = 0.0f, e1 = 0.0f;
#pragma unroll
    for (int j = 0; j < 4; j++) {
        const float w0 = wyz[j] * gx;
        const float w1 = wyz[j] * fx;
        e0 = fmaf(w0, f0[j].x, fmaf(w1, f1[j].x, e0));
        e1 = fmaf(w0, f0[j].y, fmaf(w1, f1[j].y, e1));
    }

    const u64 a0 = pk2(e0, e0), a1 = pk2(e1, e1);
    const u64* __restrict__ r0 = (const u64*)&cW0[(2 * l) * HID];
    const u64* __restrict__ r1 = (const u64*)&cW0[(2 * l + 1) * HID];
#pragma unroll
    for (int j = 0; j < HID / 2; j++) {
        acc[j] = ffma2(a1, r1[j], ffma2(a0, r0[j], acc[j]));
    }
}

__global__ void __launch_bounds__(128) sdf_fused(
    const float* __restrict__ x,
    const float* __restrict__ tables,
    float* __restrict__ out,
    int npts, LevelParams lp)
{
    __shared__ __align__(16) float sH[HID * 128];    // 32 KB hidden, transposed [i][tid]

    const int pt = blockIdx.x * blockDim.x + threadIdx.x;
    if (pt >= npts) return;

    const float x0 = (x[3 * pt + 0] + 1.0f) * 0.5f;
    const float y0 = (x[3 * pt + 1] + 1.0f) * 0.5f;
    const float z0 = (x[3 * pt + 2] + 1.0f) * 0.5f;

    u64 acc[HID / 2];
#pragma unroll
    for (int j = 0; j < HID / 2; j++) acc[j] = 0ull;

    // ---- dense levels: one LDG.128 per x-pair from g_Q ----
#pragma unroll
    for (int l = 0; l < NDENSE; l++) {
        const float rf = lp.resf[l];
        const float px = x0 * rf, py = y0 * rf, pz = z0 * rf;
        const float fpx = floorf(px), fpy = floorf(py), fpz = floorf(pz);
        const float fx = px - fpx, fy = py - fpy, fz = pz - fpz;
        const unsigned cx = (unsigned)fpx, cy = (unsigned)fpy, cz = (unsigned)fpz;

        const unsigned s1 = lp.s1[l], s2 = lp.s2[l];
        const unsigned ay0 = cy * s1, az0 = cz * s2;
        const float4* __restrict__ Q = g_Q + lp.qoff[l];

        unsigned b[4];
        b[0] = cx + ay0 + az0;
        b[1] = b[0] + s2;
        b[2] = b[0] + s1;
        b[3] = b[2] + s2;

        float2 f0[4], f1[4];
#pragma unroll
        for (int j = 0; j < 4; j++) {
            const float4 q = __ldg(&Q[b[j]]);
            f0[j] = make_float2(q.x, q.y);
            f1[j] = make_float2(q.z, q.w);
        }
        level_accumulate(l, f0, f1, fx, fy, fz, acc);
    }

    // ---- hashed levels: pair via h(x+1)=h(x)^1 when cx is even ----
#pragma unroll 1
    for (int l = NDENSE; l < NLEV; l++) {
        const float rf = lp.resf[l];
        const float px = x0 * rf, py = y0 * rf, pz = z0 * rf;
        const float fpx = floorf(px), fpy = floorf(py), fpz = floorf(pz);
        const float fx = px - fpx, fy = py - fpy, fz = pz - fpz;
        const unsigned cx = (unsigned)fpx, cy = (unsigned)fpy, cz = (unsigned)fpz;

        const float2* __restrict__ tab2 = ((const float2*)tables) + (size_t)l * TSIZE;
        const float4* __restrict__ tab4 = (const float4*)tab2;
        const unsigned m = TSIZE - 1u;

        const unsigned ay0 = cy * P2, az0 = cz * P3;
        unsigned s[4];
        s[0] = ay0 ^ az0;
        s[1] = ay0 ^ (az0 + P3);
        s[2] = (ay0 + P2) ^ az0;
        s[3] = (ay0 + P2) ^ (az0 + P3);

        float2 f0[4], f1[4];
        if ((cx & 1u) == 0u) {
#pragma unroll
            for (int j = 0; j < 4; j++) {
                const unsigned i0 = (cx ^ s[j]) & m;
                const float4 q = __ldg(&tab4[i0 >> 1]);
                const bool hi = (i0 & 1u) != 0u;
                f0[j] = hi ? make_float2(q.z, q.w) : make_float2(q.x, q.y);
                f1[j] = hi ? make_float2(q.x, q.y) : make_float2(q.z, q.w);
            }
        } else {
            const unsigned cx1 = cx + 1u;
#pragma unroll
            for (int j = 0; j < 4; j++) {
                const unsigned i0 = (cx  ^ s[j]) & m;
                const unsigned i1 = (cx1 ^ s[j]) & m;
                f0[j] = __ldg(&tab2[i0]);
                f1[j] = __ldg(&tab2[i1]);
            }
        }
        level_accumulate(l, f0, f1, fx, fy, fz, acc);
    }

    // ---- ReLU -> hidden to smem (transposed), reset accumulators ----
    {
        const int t = threadIdx.x;
#pragma unroll
        for (int j = 0; j < HID / 2; j++) {
            float a, b; upk2(acc[j], a, b);
            sH[(2 * j) * 128 + t]     = fmaxf(a, 0.0f);
            sH[(2 * j + 1) * 128 + t] = fmaxf(b, 0.0f);
            acc[j] = 0ull;
        }
    }

    // ---- layer 1: 64x64, weights from cbank ----
    {
        const int t = threadIdx.x;
#pragma unroll 8
        for (int i = 0; i < HID; i++) {
            const float hi = sH[i * 128 + t];
            const u64 ai = pk2(hi, hi);
            const u64* __restrict__ r = (const u64*)&cW1[i * HID];
#pragma unroll
            for (int j = 0; j < HID / 2; j++) {
                acc[j] = ffma2(ai, r[j], acc[j]);
            }
        }
    }

    // ---- ReLU + layer 2 (64 -> 1) ----
    float res = 0.0f;
#pragma unroll
    for (int j = 0; j < HID / 2; j++) {
        float a, b; upk2(acc[j], a, b);
        res = fmaf(fmaxf(a, 0.0f), cW2[2 * j], res);
        res = fmaf(fmaxf(b, 0.0f), cW2[2 * j + 1], res);
    }
    out[pt] = res;
}

static LevelParams make_params(unsigned* qtotal_out) {
    LevelParams lp;
    unsigned qoff = 0;
    for (int l = 0; l < NLEV; l++) {
        const double r = floor(16.0 * pow(1.3819, (double)l));
        const int res = (int)r;
        lp.resf[l] = (float)res;
        const unsigned s1 = (unsigned)(res + 1);
        lp.s1[l] = s1;
        lp.s2[l] = s1 * s1;
        if (l < NDENSE) {
            const unsigned cnt = s1 * s1 * s1 + s1 * s1 + s1 + 2u;
            lp.qoff[l] = qoff;
            lp.qcnt[l] = cnt;
            qoff += cnt;
        }
    }
    *qtotal_out = qoff;
    return lp;
}

extern "C" void kernel_launch(void* const* d_in, const int* in_sizes, int n_in,
                              void* d_out, int out_size) {
    const float* x      = (const float*)d_in[0];
    const float* tables = (const float*)d_in[1];
    const float* W0     = (const float*)d_in[2];
    const float* W1     = (const float*)d_in[3];
    const float* W2     = (const float*)d_in[4];
    float* out = (float*)d_out;

    const int npts = out_size;
    unsigned qtotal = 0;
    LevelParams lp = make_params(&qtotal);

    // Stage weights into the constant bank (device-to-device async: graph-capturable).
    cudaMemcpyToSymbolAsync(cW0, W0, ENC * HID * sizeof(float), 0,
                            cudaMemcpyDeviceToDevice, 0);
    cudaMemcpyToSymbolAsync(cW1, W1, HID * HID * sizeof(float), 0,
                            cudaMemcpyDeviceToDevice, 0);
    cudaMemcpyToSymbolAsync(cW2, W2, HID * sizeof(float), 0,
                            cudaMemcpyDeviceToDevice, 0);

    {
        const int bt = 256;
        const int bg = (int)((qtotal + bt - 1) / bt);
        build_q<<<bg, bt>>>((const float2*)tables, lp, qtotal);
    }

    const int block = 128;
    const int grid = (npts + block - 1) / block;
    sdf_fused<<<grid, block>>>(x, tables, out, npts, lp);
}

// round 4
// speedup vs baseline: 1.8527x; 1.8527x over previous
#include <cuda_runtime.h>
#include <cmath>
#include <stdint.h>

#define NLEV   16
#define NDENSE 5
#define TSIZE  (1u << 19)
#define HID    64
#define ENC    32
#define P2     2654435761u
#define P3     805459861u
#define NMAX   1048576
#define NBINS  32768

typedef unsigned long long u64;

// ---- device scratch (static, no runtime allocation) ----
#define QCAP 339072
__device__ float4   g_Q[QCAP];          // dense-level x-pair tables
__device__ int      g_hist[NBINS];      // morton histogram / running offsets
__device__ int      g_bin[NMAX];        // per-point bin id
__device__ float4   g_xs[NMAX];         // sorted (x01, y01, z01, orig_idx)

struct LevelParams {
    float    resf[NLEV];
    unsigned s1[NLEV];
    unsigned s2[NLEV];
    unsigned qoff[NDENSE];
    unsigned qcnt[NDENSE];
};

__device__ __forceinline__ u64 pk2(float a, float b) {
    u64 r; asm("mov.b64 %0, {%1,%2};" : "=l"(r) : "f"(a), "f"(b)); return r;
}
__device__ __forceinline__ void upk2(u64 v, float& a, float& b) {
    asm("mov.b64 {%0,%1}, %2;" : "=f"(a), "=f"(b) : "l"(v));
}
__device__ __forceinline__ u64 ffma2(u64 a, u64 b, u64 c) {
    u64 d; asm("fma.rn.f32x2 %0, %1, %2, %3;" : "=l"(d) : "l"(a), "l"(b), "l"(c)); return d;
}

// ---------- prologue: dense pair tables ----------
__global__ void build_q(const float2* __restrict__ tables, LevelParams lp, unsigned total) {
    unsigned i = blockIdx.x * blockDim.x + threadIdx.x;
    if (i >= total) return;
    int l = 0; unsigned base = 0;
#pragma unroll
    for (int k = 0; k < NDENSE; k++) {
        unsigned o = lp.qoff[k];
        if (i >= o && i < o + lp.qcnt[k]) { l = k; base = o; }
    }
    unsigned j = i - base;
    const float2* __restrict__ tab = tables + (size_t)l * TSIZE;
    float2 a = __ldg(&tab[j]);
    float2 b = __ldg(&tab[j + 1]);
    g_Q[i] = make_float4(a.x, a.y, b.x, b.y);
}

// ---------- morton binning ----------
__device__ __forceinline__ unsigned part3(unsigned v) {
    v &= 31u;
    unsigned r = 0;
#pragma unroll
    for (int b = 0; b < 5; b++) r |= ((v >> b) & 1u) << (3 * b);
    return r;
}

__global__ void bin_points(const float* __restrict__ x, int npts) {
    int p = blockIdx.x * blockDim.x + threadIdx.x;
    if (p >= npts) return;
    float x0 = (x[3 * p + 0] + 1.0f) * 0.5f;
    float y0 = (x[3 * p + 1] + 1.0f) * 0.5f;
    float z0 = (x[3 * p + 2] + 1.0f) * 0.5f;
    unsigned bx = min(31, max(0, (int)floorf(x0 * 32.0f)));
    unsigned by = min(31, max(0, (int)floorf(y0 * 32.0f)));
    unsigned bz = min(31, max(0, (int)floorf(z0 * 32.0f)));
    unsigned bin = part3(bx) | (part3(by) << 1) | (part3(bz) << 2);
    g_bin[p] = (int)bin;
    atomicAdd(&g_hist[bin], 1);
}

// exclusive prefix sum over NBINS (single block, 1024 threads, 32 bins each)
__global__ void scan_bins() {
    __shared__ int warp_tot[32];
    const int t = threadIdx.x;
    const int base = t * (NBINS / 1024);
    int loc[NBINS / 1024];
    int ts = 0;
#pragma unroll
    for (int k = 0; k < NBINS / 1024; k++) { loc[k] = g_hist[base + k]; ts += loc[k]; }
    int v = ts;
    for (int d = 1; d < 32; d <<= 1) {
        int n = __shfl_up_sync(0xffffffffu, v, d);
        if ((t & 31) >= d) v += n;
    }
    if ((t & 31) == 31) warp_tot[t >> 5] = v;
    __syncthreads();
    if (t < 32) {
        int w = warp_tot[t];
        for (int d = 1; d < 32; d <<= 1) {
            int n = __shfl_up_sync(0xffffffffu, w, d);
            if (t >= d) w += n;
        }
        warp_tot[t] = w;
    }
    __syncthreads();
    int excl = v - ts + ((t >> 5) ? warp_tot[(t >> 5) - 1] : 0);
    int run = excl;
#pragma unroll
    for (int k = 0; k < NBINS / 1024; k++) { g_hist[base + k] = run; run += loc[k]; }
}

__global__ void scatter_points(const float* __restrict__ x, int npts) {
    int p = blockIdx.x * blockDim.x + threadIdx.x;
    if (p >= npts) return;
    int bin = g_bin[p];
    int pos = atomicAdd(&g_hist[bin], 1);
    float x0 = (x[3 * p + 0] + 1.0f) * 0.5f;
    float y0 = (x[3 * p + 1] + 1.0f) * 0.5f;
    float z0 = (x[3 * p + 2] + 1.0f) * 0.5f;
    g_xs[pos] = make_float4(x0, y0, z0, __int_as_float(p));
}

// ---------- main fused kernel: 128 threads, 256 points/block ----------
__global__ void __launch_bounds__(128) sdf_fused(
    const float* __restrict__ tables,
    const float* __restrict__ W0,
    const float* __restrict__ W1,
    const float* __restrict__ W2,
    float* __restrict__ out,
    int npts, LevelParams lp)
{
    extern __shared__ __align__(16) float smem[];
    float* sW0 = smem;                       // 2048
    float* sW1 = sW0 + ENC * HID;            // 4096
    float* sW2 = sW1 + HID * HID;            // 64
    float* sH  = sW2 + HID;                  // 64*256 (enc uses first 32*256)

    {
        int t = threadIdx.x;
        float4*       s0 = (float4*)sW0;  const float4* g0 = (const float4*)W0;
        for (int i = t; i < ENC * HID / 4; i += 128) s0[i] = g0[i];
        float4*       s1 = (float4*)sW1;  const float4* g1 = (const float4*)W1;
        for (int i = t; i < HID * HID / 4; i += 128) s1[i] = g1[i];
        if (t < HID / 4) ((float4*)sW2)[t] = ((const float4*)W2)[t];
    }
    __syncthreads();

    const int t = threadIdx.x;
    const int base = blockIdx.x * 256;
    int orig0 = -1, orig1 = -1;

    // ================= gather phase: both points, enc -> smem =================
#pragma unroll 1
    for (int ph = 0; ph < 2; ph++) {
        const int pt = base + ph * 128 + t;
        const int col = ph * 128 + t;
        if (pt >= npts) continue;
        const float4 xs = g_xs[pt];
        if (ph == 0) orig0 = __float_as_int(xs.w); else orig1 = __float_as_int(xs.w);
        const float x0 = xs.x, y0 = xs.y, z0 = xs.z;

        // dense levels
#pragma unroll
        for (int l = 0; l < NDENSE; l++) {
            const float rf = lp.resf[l];
            const float px = x0 * rf, py = y0 * rf, pz = z0 * rf;
            const float fpx = floorf(px), fpy = floorf(py), fpz = floorf(pz);
            const float fx = px - fpx, fy = py - fpy, fz = pz - fpz;
            const unsigned cx = (unsigned)fpx, cy = (unsigned)fpy, cz = (unsigned)fpz;

            const unsigned s1 = lp.s1[l], s2 = lp.s2[l];
            const float4* __restrict__ Q = g_Q + lp.qoff[l];
            const unsigned b0 = cx + cy * s1 + cz * s2;
            const unsigned bb[4] = {b0, b0 + s2, b0 + s1, b0 + s1 + s2};

            float4 q[4];
#pragma unroll
            for (int j = 0; j < 4; j++) q[j] = __ldg(&Q[bb[j]]);

            const float gx = 1.0f - fx, gy = 1.0f - fy, gz = 1.0f - fz;
            const float wyz[4] = {gy * gz, gy * fz, fy * gz, fy * fz};
            float e0 = 0.0f, e1 = 0.0f;
#pragma unroll
            for (int j = 0; j < 4; j++) {
                const float w0 = wyz[j] * gx, w1 = wyz[j] * fx;
                e0 = fmaf(w0, q[j].x, fmaf(w1, q[j].z, e0));
                e1 = fmaf(w0, q[j].y, fmaf(w1, q[j].w, e1));
            }
            sH[(2 * l) * 256 + col] = e0;
            sH[(2 * l + 1) * 256 + col] = e1;
        }

        // hashed levels
#pragma unroll 1
        for (int l = NDENSE; l < NLEV; l++) {
            const float rf = lp.resf[l];
            const float px = x0 * rf, py = y0 * rf, pz = z0 * rf;
            const float fpx = floorf(px), fpy = floorf(py), fpz = floorf(pz);
            const float fx = px - fpx, fy = py - fpy, fz = pz - fpz;
            const unsigned cx = (unsigned)fpx, cy = (unsigned)fpy, cz = (unsigned)fpz;

            const float2* __restrict__ tab2 = ((const float2*)tables) + (size_t)l * TSIZE;
            const float4* __restrict__ tab4 = (const float4*)tab2;
            const unsigned m = TSIZE - 1u;
            const unsigned ay0 = cy * P2, az0 = cz * P3;
            const unsigned s[4] = {ay0 ^ az0, ay0 ^ (az0 + P3),
                                   (ay0 + P2) ^ az0, (ay0 + P2) ^ (az0 + P3)};

            float2 f0[4], f1[4];
            if ((cx & 1u) == 0u) {
#pragma unroll
                for (int j = 0; j < 4; j++) {
                    const unsigned i0 = (cx ^ s[j]) & m;
                    const float4 q = __ldg(&tab4[i0 >> 1]);
                    const bool hi = (i0 & 1u) != 0u;
                    f0[j] = hi ? make_float2(q.z, q.w) : make_float2(q.x, q.y);
                    f1[j] = hi ? make_float2(q.x, q.y) : make_float2(q.z, q.w);
                }
            } else {
                const unsigned cx1 = cx + 1u;
#pragma unroll
                for (int j = 0; j < 4; j++) {
                    f0[j] = __ldg(&tab2[(cx  ^ s[j]) & m]);
                    f1[j] = __ldg(&tab2[(cx1 ^ s[j]) & m]);
                }
            }

            const float gx = 1.0f - fx, gy = 1.0f - fy, gz = 1.0f - fz;
            const float wyz[4] = {gy * gz, gy * fz, fy * gz, fy * fz};
            float e0 = 0.0f, e1 = 0.0f;
#pragma unroll
            for (int j = 0; j < 4; j++) {
                const float w0 = wyz[j] * gx, w1 = wyz[j] * fx;
                e0 = fmaf(w0, f0[j].x, fmaf(w1, f1[j].x, e0));
                e1 = fmaf(w0, f0[j].y, fmaf(w1, f1[j].y, e1));
            }
            sH[(2 * l) * 256 + col] = e0;
            sH[(2 * l + 1) * 256 + col] = e1;
        }
    }

    // ================= layer 0: weight-shared across both points =================
    u64 accA[HID / 2], accB[HID / 2];
#pragma unroll
    for (int j = 0; j < HID / 2; j++) { accA[j] = 0ull; accB[j] = 0ull; }

#pragma unroll 2
    for (int e = 0; e < ENC; e++) {
        const float hA = sH[e * 256 + t];
        const float hB = sH[e * 256 + 128 + t];
        const u64 aA = pk2(hA, hA), aB = pk2(hB, hB);
        const ulonglong2* __restrict__ r = (const ulonglong2*)&sW0[e * HID];
#pragma unroll
        for (int j = 0; j < HID / 4; j++) {
            const ulonglong2 v = r[j];
            accA[2 * j]     = ffma2(aA, v.x, accA[2 * j]);
            accA[2 * j + 1] = ffma2(aA, v.y, accA[2 * j + 1]);
            accB[2 * j]     = ffma2(aB, v.x, accB[2 * j]);
            accB[2 * j + 1] = ffma2(aB, v.y, accB[2 * j + 1]);
        }
    }

    // ReLU -> h into smem (overwrites enc region; threads touch only their own columns)
#pragma unroll
    for (int j = 0; j < HID / 2; j++) {
        float a, b; upk2(accA[j], a, b);
        sH[(2 * j) * 256 + t]     = fmaxf(a, 0.0f);
        sH[(2 * j + 1) * 256 + t] = fmaxf(b, 0.0f);
        upk2(accB[j], a, b);
        sH[(2 * j) * 256 + 128 + t]     = fmaxf(a, 0.0f);
        sH[(2 * j + 1) * 256 + 128 + t] = fmaxf(b, 0.0f);
        accA[j] = 0ull; accB[j] = 0ull;
    }

    // ================= layer 1: weight-shared across both points =================
#pragma unroll 4
    for (int i = 0; i < HID; i++) {
        const float hA = sH[i * 256 + t];
        const float hB = sH[i * 256 + 128 + t];
        const u64 aA = pk2(hA, hA), aB = pk2(hB, hB);
        const ulonglong2* __restrict__ r = (const ulonglong2*)&sW1[i * HID];
#pragma unroll
        for (int j = 0; j < HID / 4; j++) {
            const ulonglong2 v = r[j];
            accA[2 * j]     = ffma2(aA, v.x, accA[2 * j]);
            accA[2 * j + 1] = ffma2(aA, v.y, accA[2 * j + 1]);
            accB[2 * j]     = ffma2(aB, v.x, accB[2 * j]);
            accB[2 * j + 1] = ffma2(aB, v.y, accB[2 * j + 1]);
        }
    }

    // ================= ReLU + layer 2 =================
    float resA = 0.0f, resB = 0.0f;
#pragma unroll
    for (int j = 0; j < HID / 2; j++) {
        const float w0 = sW2[2 * j], w1 = sW2[2 * j + 1];
        float a, b; upk2(accA[j], a, b);
        resA = fmaf(fmaxf(a, 0.0f), w0, resA);
        resA = fmaf(fmaxf(b, 0.0f), w1, resA);
        upk2(accB[j], a, b);
        resB = fmaf(fmaxf(a, 0.0f), w0, resB);
        resB = fmaf(fmaxf(b, 0.0f), w1, resB);
    }
    if (orig0 >= 0) out[orig0] = resA;
    if (orig1 >= 0) out[orig1] = resB;
}

static LevelParams make_params(unsigned* qtotal_out) {
    LevelParams lp;
    unsigned qoff = 0;
    for (int l = 0; l < NLEV; l++) {
        const double r = floor(16.0 * pow(1.3819, (double)l));
        const int res = (int)r;
        lp.resf[l] = (float)res;
        const unsigned s1 = (unsigned)(res + 1);
        lp.s1[l] = s1;
        lp.s2[l] = s1 * s1;
        if (l < NDENSE) {
            const unsigned cnt = s1 * s1 * s1 + s1 * s1 + s1 + 2u;
            lp.qoff[l] = qoff;
            lp.qcnt[l] = cnt;
            qoff += cnt;
        }
    }
    *qtotal_out = qoff;
    return lp;
}

extern "C" void kernel_launch(void* const* d_in, const int* in_sizes, int n_in,
                              void* d_out, int out_size) {
    const float* x      = (const float*)d_in[0];
    const float* tables = (const float*)d_in[1];
    const float* W0     = (const float*)d_in[2];
    const float* W1     = (const float*)d_in[3];
    const float* W2     = (const float*)d_in[4];
    float* out = (float*)d_out;

    const int npts = out_size;
    unsigned qtotal = 0;
    LevelParams lp = make_params(&qtotal);

    static void* hist_addr = nullptr;
    if (!hist_addr) cudaGetSymbolAddress(&hist_addr, g_hist);

    const int smem_bytes = (ENC * HID + HID * HID + HID + HID * 256) * (int)sizeof(float);
    static bool attr_set = false;
    if (!attr_set) {
        cudaFuncSetAttribute(sdf_fused, cudaFuncAttributeMaxDynamicSharedMemorySize,
                             smem_bytes);
        attr_set = true;
    }

    // ---- morton counting sort (deterministic output: per-point results
    //      independent of intra-bin order) ----
    cudaMemsetAsync(hist_addr, 0, NBINS * sizeof(int), 0);
    bin_points<<<(npts + 255) / 256, 256>>>(x, npts);
    scan_bins<<<1, 1024>>>();
    scatter_points<<<(npts + 255) / 256, 256>>>(x, npts);

    // ---- dense pair tables ----
    build_q<<<(qtotal + 255) / 256, 256>>>((const float2*)tables, lp, qtotal);

    // ---- fused main ----
    const int grid = (npts + 255) / 256;
    sdf_fused<<<grid, 128, smem_bytes>>>(tables, W0, W1, W2, out, npts, lp);
}